// round 2
// baseline (speedup 1.0000x reference)
#include <cuda_runtime.h>
#include <cstdint>
#include <cstddef>

#define NN 512
#define BB 128
#define TT 1000
#define NI 6
#define WPAD 516
#define CTAS 128
#define THREADS 256

// ---- shared memory layout (bytes) ----
#define OFF_W    0
#define SZ_W     (64*WPAD*4)            // 132096: W_rec slice [64][516]
#define OFF_ST   (SZ_W)                 // 132096: sT double buffer [2][512][8]
#define SZ_ST1   (NN*8*4)               // 16384
#define OFF_PART (OFF_ST + 2*SZ_ST1)    // 164864: partials [8w][4rp][64n] f32x2
#define SZ_PART  (8*4*64*8)             // 16384
#define OFF_WINP (OFF_PART + SZ_PART)   // 181248: W_inp slice [64][6]
#define SZ_WINP  (64*NI*4)              // 1536
#define OFF_XSHT (OFF_WINP + SZ_WINP)   // 182784: (u+noise) transposed [6][8]
#define SZ_XSHT  (NI*8*4)               // 192
#define SMEM_TOTAL (OFF_XSHT + SZ_XSHT) // 182976

typedef unsigned long long ull;

// ---- SMEM / f32x2 helpers ----
__device__ __forceinline__ float4 lds128(uint32_t a) {
    float4 v;
    asm volatile("ld.shared.v4.f32 {%0,%1,%2,%3},[%4];"
                 : "=f"(v.x), "=f"(v.y), "=f"(v.z), "=f"(v.w) : "r"(a));
    return v;
}
__device__ __forceinline__ void lds2u64(uint32_t a, ull& x, ull& y) {
    asm volatile("ld.shared.v2.u64 {%0,%1},[%2];" : "=l"(x), "=l"(y) : "r"(a));
}
__device__ __forceinline__ ull ldsu64(uint32_t a) {
    ull v; asm volatile("ld.shared.u64 %0,[%1];" : "=l"(v) : "r"(a)); return v;
}
__device__ __forceinline__ float ldsf(uint32_t a) {
    float v; asm volatile("ld.shared.f32 %0,[%1];" : "=f"(v) : "r"(a)); return v;
}
__device__ __forceinline__ void stsu64(uint32_t a, ull v) {
    asm volatile("st.shared.u64 [%0],%1;" :: "r"(a), "l"(v) : "memory");
}
__device__ __forceinline__ void stsf(uint32_t a, float v) {
    asm volatile("st.shared.f32 [%0],%1;" :: "r"(a), "f"(v) : "memory");
}
__device__ __forceinline__ ull dup2(float w) {
    ull d; unsigned int b = __float_as_uint(w);
    asm("mov.b64 %0,{%1,%1};" : "=l"(d) : "r"(b)); return d;
}
__device__ __forceinline__ ull fma2(ull a, ull b, ull c) {
    ull d; asm("fma.rn.f32x2 %0,%1,%2,%3;" : "=l"(d) : "l"(a), "l"(b), "l"(c)); return d;
}
__device__ __forceinline__ ull add2(ull a, ull b) {
    ull d; asm("add.rn.f32x2 %0,%1,%2;" : "=l"(d) : "l"(a), "l"(b)); return d;
}
__device__ __forceinline__ void unpack2(ull v, float& lo, float& hi) {
    unsigned int a, b; asm("mov.b64 {%0,%1},%2;" : "=r"(a), "=r"(b) : "l"(v));
    lo = __uint_as_float(a); hi = __uint_as_float(b);
}
__device__ __forceinline__ ull pack2(float lo, float hi) {
    ull d;
    asm("mov.b64 %0,{%1,%2};" : "=l"(d)
        : "r"(__float_as_uint(lo)), "r"(__float_as_uint(hi)));
    return d;
}

// ============================================================================
// Kernel A: the recurrence. 16 clusters x 8 CTAs. Cluster g owns batch rows
// [8g, 8g+8); CTA rank r owns output columns [64r, 64r+64). W_rec slice is
// SMEM-resident for the whole kernel. State is replicated per CTA as
// sT[k][8 rows] (double buffered); each step every CTA broadcasts its 8x64
// s_new slice to all 8 ranks via DSMEM, then barrier.cluster.
// ============================================================================
__global__ void __launch_bounds__(THREADS, 1) __cluster_dims__(8, 1, 1)
rnn_dyn_kernel(const float* __restrict__ u,
               const float* __restrict__ rec_noise,
               const float* __restrict__ inp_noise,
               const float* __restrict__ W_rec,
               const float* __restrict__ W_inp,
               const float* __restrict__ y_init,
               float* __restrict__ states)
{
    extern __shared__ unsigned char smraw[];
    const uint32_t sb = (uint32_t)__cvta_generic_to_shared(smraw);

    const int tid  = threadIdx.x;
    const int rank = blockIdx.x & 7;   // CTA rank within cluster (x-major)
    const int g    = blockIdx.x >> 3;  // cluster id

    // ---- prologue: load W_rec slice (padded rows), W_inp slice, init sT[0] ----
    for (int idx = tid; idx < 64 * NN; idx += THREADS) {
        int nl = idx >> 9, k = idx & 511;
        stsf(sb + OFF_W + (uint32_t)(nl * WPAD + k) * 4,
             W_rec[((size_t)(rank * 64 + nl) << 9) + k]);
    }
    for (int idx = tid; idx < 64 * NI; idx += THREADS) {
        stsf(sb + OFF_WINP + (uint32_t)idx * 4, W_inp[(size_t)rank * 64 * NI + idx]);
    }
    for (int idx = tid; idx < NN * 8; idx += THREADS) {
        stsf(sb + OFF_ST + (uint32_t)idx * 4, y_init[idx >> 3]);  // sT[0][k][r] = y_init[k]
    }

    // per-thread combine-phase identity: thread owns (column n, row-pair rp)
    const int n   = tid & 63;
    const int rp  = tid >> 6;          // 0..3 -> rows (2rp, 2rp+1)
    const int gn  = rank * 64 + n;     // global column
    const int b0  = g * 8 + 2 * rp;
    const int b1  = b0 + 1;

    // states[:,0,:] = y_init
    {
        float y0 = y_init[gn];
        states[(size_t)b0 * TT * NN + gn] = y0;
        states[(size_t)b1 * TT * NN + gn] = y0;
    }
    __syncthreads();

    // GEMM-phase identity: warp w handles k-chunk [64w,64w+64), lane nl owns
    // columns nl and nl+32 (local), all 8 rows as 4 f32x2 row-pairs.
    const int w  = tid >> 5;
    const int nl = tid & 31;
    const uint32_t aW0 = sb + OFF_W + (uint32_t)(nl * WPAD + w * 64) * 4;
    const uint32_t aW1 = sb + OFF_W + (uint32_t)((nl + 32) * WPAD + w * 64) * 4;
    const uint32_t aPartW = sb + OFF_PART + (uint32_t)(w * 4) * 64 * 8;
    const uint32_t aPartC = sb + OFF_PART + (uint32_t)(rp * 64 + n) * 8;

    for (int t = 0; t < TT - 1; ++t) {
        const int cur = t & 1;
        const uint32_t aScur = sb + OFF_ST + (uint32_t)cur * SZ_ST1;
        const uint32_t aSnxt = sb + OFF_ST + (uint32_t)(cur ^ 1) * SZ_ST1;

        // ---- prefetch this step's noise (consumed ~3k cycles later) ----
        const float rn0 = rec_noise[((size_t)b0 * TT + t) * NN + gn];
        const float rn1 = rec_noise[((size_t)b1 * TT + t) * NN + gn];
        if (tid < 48) {   // (u + inp_noise) -> xshT[i][r]
            int r = tid / 6, i = tid - r * 6;
            size_t xidx = ((size_t)(g * 8 + r) * TT + t) * NI + i;
            stsf(sb + OFF_XSHT + (uint32_t)(i * 8 + r) * 4, u[xidx] + inp_noise[xidx]);
        }

        // ---- main GEMM: partial dot over this warp's 64-wide k chunk ----
        {
            ull a00 = 0, a01 = 0, a02 = 0, a03 = 0;
            ull a10 = 0, a11 = 0, a12 = 0, a13 = 0;
            const uint32_t aS = aScur + (uint32_t)(w * 64) * 32;
#pragma unroll 4
            for (int it = 0; it < 16; ++it) {
                float4 w0 = lds128(aW0 + it * 16);
                float4 w1 = lds128(aW1 + it * 16);
                float wa0[4] = { w0.x, w0.y, w0.z, w0.w };
                float wa1[4] = { w1.x, w1.y, w1.z, w1.w };
                uint32_t ak = aS + (uint32_t)it * 128;
#pragma unroll
                for (int kk = 0; kk < 4; ++kk) {
                    ull sA, sB, sC, sD;
                    lds2u64(ak + kk * 32,      sA, sB);   // rows 0-1, 2-3
                    lds2u64(ak + kk * 32 + 16, sC, sD);   // rows 4-5, 6-7
                    ull d0 = dup2(wa0[kk]);
                    ull d1 = dup2(wa1[kk]);
                    a00 = fma2(d0, sA, a00); a01 = fma2(d0, sB, a01);
                    a02 = fma2(d0, sC, a02); a03 = fma2(d0, sD, a03);
                    a10 = fma2(d1, sA, a10); a11 = fma2(d1, sB, a11);
                    a12 = fma2(d1, sC, a12); a13 = fma2(d1, sD, a13);
                }
            }
            // partials: part[w][rp][n]
            stsu64(aPartW + (uint32_t)(0 * 64 + nl) * 8, a00);
            stsu64(aPartW + (uint32_t)(1 * 64 + nl) * 8, a01);
            stsu64(aPartW + (uint32_t)(2 * 64 + nl) * 8, a02);
            stsu64(aPartW + (uint32_t)(3 * 64 + nl) * 8, a03);
            stsu64(aPartW + (uint32_t)(0 * 64 + nl + 32) * 8, a10);
            stsu64(aPartW + (uint32_t)(1 * 64 + nl + 32) * 8, a11);
            stsu64(aPartW + (uint32_t)(2 * 64 + nl + 32) * 8, a12);
            stsu64(aPartW + (uint32_t)(3 * 64 + nl + 32) * 8, a13);
        }
        __syncthreads();

        // ---- combine k-split partials + input projection ----
        ull pre2 = ldsu64(aPartC);
#pragma unroll
        for (int ww = 1; ww < 8; ++ww)
            pre2 = add2(pre2, ldsu64(aPartC + (uint32_t)ww * 4 * 64 * 8));
#pragma unroll
        for (int i = 0; i < NI; ++i) {
            float wv = ldsf(sb + OFF_WINP + (uint32_t)(n * NI + i) * 4);
            ull x2 = ldsu64(sb + OFF_XSHT + (uint32_t)(i * 8 + 2 * rp) * 4);
            pre2 = fma2(dup2(wv), x2, pre2);
        }

        // ---- state update ----
        float plo, phi, slo, shi;
        unpack2(pre2, plo, phi);
        unpack2(ldsu64(aScur + (uint32_t)(gn * 8 + 2 * rp) * 4), slo, shi);
        float nlo = 0.9f * slo + 0.1f * (fmaxf(plo, 0.0f) + rn0);
        float nhi = 0.9f * shi + 0.1f * (fmaxf(phi, 0.0f) + rn1);

        // write states[:, t+1, :]
        size_t so = (size_t)(t + 1) * NN + gn;
        states[(size_t)b0 * TT * NN + so] = nlo;
        states[(size_t)b1 * TT * NN + so] = nhi;

        // ---- broadcast s_new slice into every rank's next buffer ----
        ull snew2 = pack2(nlo, nhi);
        uint32_t dsto = aSnxt + (uint32_t)(gn * 8 + 2 * rp) * 4;
#pragma unroll
        for (int cr = 0; cr < 8; ++cr) {
            uint32_t ra;
            asm volatile("mapa.shared::cluster.u32 %0,%1,%2;" : "=r"(ra) : "r"(dsto), "r"(cr));
            asm volatile("st.shared::cluster.u64 [%0],%1;" :: "r"(ra), "l"(snew2) : "memory");
        }

        // ---- cluster barrier: release DSMEM stores, sync all 8 CTAs ----
        asm volatile("barrier.cluster.arrive.aligned;" ::: "memory");
        asm volatile("barrier.cluster.wait.aligned;" ::: "memory");
    }
}

// ============================================================================
// Kernel B: outputs[b,t] = dot(states[b,t,:], W_out). One warp per (b,t).
// ============================================================================
__global__ void __launch_bounds__(256) out_proj_kernel(
    const float* __restrict__ states,
    const float* __restrict__ W_out,
    float* __restrict__ out)
{
    int warp = (blockIdx.x * blockDim.x + threadIdx.x) >> 5;  // 0 .. B*T-1
    int lane = threadIdx.x & 31;
    const float4* sp = (const float4*)(states + (size_t)warp * NN);
    const float4* wp = (const float4*)W_out;
    float acc = 0.0f;
#pragma unroll
    for (int i = 0; i < 4; ++i) {
        float4 s = sp[lane + 32 * i];
        float4 v = wp[lane + 32 * i];
        acc += s.x * v.x + s.y * v.y + s.z * v.z + s.w * v.w;
    }
#pragma unroll
    for (int o = 16; o; o >>= 1) acc += __shfl_xor_sync(0xFFFFFFFFu, acc, o);
    if (lane == 0) out[warp] = acc;
}

// ============================================================================
extern "C" void kernel_launch(void* const* d_in, const int* in_sizes, int n_in,
                              void* d_out, int out_size)
{
    const float* u         = (const float*)d_in[0];
    const float* rec_noise = (const float*)d_in[1];
    const float* inp_noise = (const float*)d_in[2];
    const float* W_rec     = (const float*)d_in[3];
    const float* W_inp     = (const float*)d_in[4];
    const float* W_out     = (const float*)d_in[5];
    const float* y_init    = (const float*)d_in[6];

    float* states  = (float*)d_out;                          // (B,T,N)
    float* outputs = states + (size_t)BB * TT * NN;          // (B,T,1)

    cudaFuncSetAttribute(rnn_dyn_kernel,
                         cudaFuncAttributeMaxDynamicSharedMemorySize, SMEM_TOTAL);

    rnn_dyn_kernel<<<CTAS, THREADS, SMEM_TOTAL>>>(
        u, rec_noise, inp_noise, W_rec, W_inp, y_init, states);

    out_proj_kernel<<<(BB * TT) / 8, 256>>>(states, W_out, outputs);
}

// round 3
// speedup vs baseline: 1.0627x; 1.0627x over previous
#include <cuda_runtime.h>
#include <cstdint>
#include <cstddef>

#define NN 512
#define BB 128
#define TT 1000
#define NI 6
#define CTAS 128
#define THREADS 512
#define WARPS 16
#define KCH 32          // k-chunk per warp

// ---- shared memory layout (bytes) ----
#define OFF_ST   0                      // sT double buffer [2][512 k][8 rows] f32
#define SZ_ST1   (NN*8*4)               // 16384
#define OFF_PART (2*SZ_ST1)             // 32768: partials [16 w][4 rp][64 n] f32x2
#define SZ_PART  (WARPS*4*64*8)         // 32768
#define OFF_WINP (OFF_PART + SZ_PART)   // 65536: W_inp slice [64][6]
#define SZ_WINP  (64*NI*4)              // 1536
#define OFF_XSHT (OFF_WINP + SZ_WINP)   // 67072: (u+noise) transposed [6][8]
#define SZ_XSHT  (NI*8*4)               // 192
#define SMEM_TOTAL (OFF_XSHT + SZ_XSHT) // 67264

typedef unsigned long long ull;

// ---- SMEM / f32x2 helpers ----
__device__ __forceinline__ void lds2u64(uint32_t a, ull& x, ull& y) {
    asm volatile("ld.shared.v2.u64 {%0,%1},[%2];" : "=l"(x), "=l"(y) : "r"(a));
}
__device__ __forceinline__ ull ldsu64(uint32_t a) {
    ull v; asm volatile("ld.shared.u64 %0,[%1];" : "=l"(v) : "r"(a)); return v;
}
__device__ __forceinline__ float ldsf(uint32_t a) {
    float v; asm volatile("ld.shared.f32 %0,[%1];" : "=f"(v) : "r"(a)); return v;
}
__device__ __forceinline__ void stsu64(uint32_t a, ull v) {
    asm volatile("st.shared.u64 [%0],%1;" :: "r"(a), "l"(v) : "memory");
}
__device__ __forceinline__ void stsf(uint32_t a, float v) {
    asm volatile("st.shared.f32 [%0],%1;" :: "r"(a), "f"(v) : "memory");
}
__device__ __forceinline__ ull dup2(float w) {
    ull d; unsigned int b = __float_as_uint(w);
    asm("mov.b64 %0,{%1,%1};" : "=l"(d) : "r"(b)); return d;
}
__device__ __forceinline__ ull fma2(ull a, ull b, ull c) {
    ull d; asm("fma.rn.f32x2 %0,%1,%2,%3;" : "=l"(d) : "l"(a), "l"(b), "l"(c)); return d;
}
__device__ __forceinline__ ull add2(ull a, ull b) {
    ull d; asm("add.rn.f32x2 %0,%1,%2;" : "=l"(d) : "l"(a), "l"(b)); return d;
}
__device__ __forceinline__ void unpack2(ull v, float& lo, float& hi) {
    unsigned int a, b; asm("mov.b64 {%0,%1},%2;" : "=r"(a), "=r"(b) : "l"(v));
    lo = __uint_as_float(a); hi = __uint_as_float(b);
}
__device__ __forceinline__ ull pack2(float lo, float hi) {
    ull d;
    asm("mov.b64 %0,{%1,%2};" : "=l"(d)
        : "r"(__float_as_uint(lo)), "r"(__float_as_uint(hi)));
    return d;
}

// ============================================================================
// Kernel A: recurrence. 16 clusters x 8 CTAs. Cluster g owns batch rows
// [8g,8g+8); CTA rank r owns output columns [64r,64r+64). W_rec slice lives
// in REGISTERS: thread (warp w, lane nl) holds W[{nl,nl+32}][32w..32w+32)
// for the entire kernel. State replicated per CTA in SMEM as sT[k][8rows],
// double-buffered; each step the 8x64 s_new slice is pushed to all ranks
// via DSMEM, then barrier.cluster.
// ============================================================================
__global__ void __launch_bounds__(THREADS, 1) __cluster_dims__(8, 1, 1)
rnn_dyn_kernel(const float* __restrict__ u,
               const float* __restrict__ rec_noise,
               const float* __restrict__ inp_noise,
               const float* __restrict__ W_rec,
               const float* __restrict__ W_inp,
               const float* __restrict__ y_init,
               float* __restrict__ states)
{
    extern __shared__ unsigned char smraw[];
    const uint32_t sb = (uint32_t)__cvta_generic_to_shared(smraw);

    const int tid  = threadIdx.x;
    const int rank = blockIdx.x & 7;   // CTA rank within cluster
    const int g    = blockIdx.x >> 3;  // cluster id

    const int w  = tid >> 5;           // warp: k-chunk [32w, 32w+32)
    const int nl = tid & 31;           // lane: local cols nl, nl+32

    // ---- W_rec slice -> registers (one time). L1 makes the strided reads cheap.
    float wr0[KCH], wr1[KCH];
    {
        const float4* p0 = (const float4*)(W_rec + ((size_t)(rank * 64 + nl)      << 9) + w * KCH);
        const float4* p1 = (const float4*)(W_rec + ((size_t)(rank * 64 + nl + 32) << 9) + w * KCH);
#pragma unroll
        for (int q = 0; q < KCH / 4; ++q) {
            float4 v0 = __ldg(p0 + q);
            float4 v1 = __ldg(p1 + q);
            wr0[4*q] = v0.x; wr0[4*q+1] = v0.y; wr0[4*q+2] = v0.z; wr0[4*q+3] = v0.w;
            wr1[4*q] = v1.x; wr1[4*q+1] = v1.y; wr1[4*q+2] = v1.z; wr1[4*q+3] = v1.w;
        }
    }

    // ---- prologue: W_inp slice, initial state ----
    for (int idx = tid; idx < 64 * NI; idx += THREADS)
        stsf(sb + OFF_WINP + (uint32_t)idx * 4, W_inp[(size_t)rank * 64 * NI + idx]);
    for (int idx = tid; idx < NN * 8; idx += THREADS)
        stsf(sb + OFF_ST + (uint32_t)idx * 4, y_init[idx >> 3]);  // sT[0][k][r]

    // combine-phase identity (tid < 256): thread owns (column n, row-pair rp)
    const int n  = tid & 63;
    const int rp = (tid >> 6) & 3;
    const int gn = rank * 64 + n;
    const int b0 = g * 8 + 2 * rp;
    const int b1 = b0 + 1;

    if (tid < 256) {                   // states[:,0,:] = y_init
        float y0 = y_init[gn];
        states[(size_t)b0 * TT * NN + gn] = y0;
        states[(size_t)b1 * TT * NN + gn] = y0;
    }
    __syncthreads();

    const uint32_t aPartW = sb + OFF_PART + (uint32_t)w * (4 * 64 * 8);
    const uint32_t aPartC = sb + OFF_PART + (uint32_t)(rp * 64 + n) * 8;

    for (int t = 0; t < TT - 1; ++t) {
        const int cur = t & 1;
        const uint32_t aScur = sb + OFF_ST + (uint32_t)cur * SZ_ST1;
        const uint32_t aSnxt = sb + OFF_ST + (uint32_t)(cur ^ 1) * SZ_ST1;

        // ---- prefetch this step's noise / inputs (consumed after the GEMM) ----
        float rn0 = 0.f, rn1 = 0.f;
        if (tid < 256) {
            rn0 = rec_noise[((size_t)b0 * TT + t) * NN + gn];
            rn1 = rec_noise[((size_t)b1 * TT + t) * NN + gn];
        }
        if (tid < 48) {   // (u + inp_noise) -> xshT[i][r]
            int r = tid / 6, i = tid - r * 6;
            size_t xidx = ((size_t)(g * 8 + r) * TT + t) * NI + i;
            stsf(sb + OFF_XSHT + (uint32_t)(i * 8 + r) * 4, u[xidx] + inp_noise[xidx]);
        }

        // ---- GEMM: warp w's 32-wide k-chunk, W from registers ----
        {
            ull a00 = 0, a01 = 0, a02 = 0, a03 = 0;
            ull a10 = 0, a11 = 0, a12 = 0, a13 = 0;
            const uint32_t aS = aScur + (uint32_t)(w * KCH) * 32;
#pragma unroll
            for (int j = 0; j < KCH; ++j) {
                ull sA, sB, sC, sD;
                lds2u64(aS + j * 32,      sA, sB);   // rows 0-1, 2-3 (broadcast)
                lds2u64(aS + j * 32 + 16, sC, sD);   // rows 4-5, 6-7
                ull d0 = dup2(wr0[j]);
                ull d1 = dup2(wr1[j]);
                a00 = fma2(d0, sA, a00); a01 = fma2(d0, sB, a01);
                a02 = fma2(d0, sC, a02); a03 = fma2(d0, sD, a03);
                a10 = fma2(d1, sA, a10); a11 = fma2(d1, sB, a11);
                a12 = fma2(d1, sC, a12); a13 = fma2(d1, sD, a13);
            }
            stsu64(aPartW + (uint32_t)(0 * 64 + nl) * 8, a00);
            stsu64(aPartW + (uint32_t)(1 * 64 + nl) * 8, a01);
            stsu64(aPartW + (uint32_t)(2 * 64 + nl) * 8, a02);
            stsu64(aPartW + (uint32_t)(3 * 64 + nl) * 8, a03);
            stsu64(aPartW + (uint32_t)(0 * 64 + nl + 32) * 8, a10);
            stsu64(aPartW + (uint32_t)(1 * 64 + nl + 32) * 8, a11);
            stsu64(aPartW + (uint32_t)(2 * 64 + nl + 32) * 8, a12);
            stsu64(aPartW + (uint32_t)(3 * 64 + nl + 32) * 8, a13);
        }
        __syncthreads();

        // ---- combine k-split partials (tree) + input proj + update (tid<256) ----
        if (tid < 256) {
            ull s0 = ldsu64(aPartC + 0u  * 2048), s1 = ldsu64(aPartC + 1u  * 2048);
            ull s2 = ldsu64(aPartC + 2u  * 2048), s3 = ldsu64(aPartC + 3u  * 2048);
            ull s4 = ldsu64(aPartC + 4u  * 2048), s5 = ldsu64(aPartC + 5u  * 2048);
            ull s6 = ldsu64(aPartC + 6u  * 2048), s7 = ldsu64(aPartC + 7u  * 2048);
            ull s8 = ldsu64(aPartC + 8u  * 2048), s9 = ldsu64(aPartC + 9u  * 2048);
            ull sa = ldsu64(aPartC + 10u * 2048), sc = ldsu64(aPartC + 11u * 2048);
            ull sd = ldsu64(aPartC + 12u * 2048), se = ldsu64(aPartC + 13u * 2048);
            ull sf = ldsu64(aPartC + 14u * 2048), sg = ldsu64(aPartC + 15u * 2048);
            s0 = add2(s0, s1); s2 = add2(s2, s3); s4 = add2(s4, s5); s6 = add2(s6, s7);
            s8 = add2(s8, s9); sa = add2(sa, sc); sd = add2(sd, se); sf = add2(sf, sg);
            s0 = add2(s0, s2); s4 = add2(s4, s6); s8 = add2(s8, sa); sd = add2(sd, sf);
            s0 = add2(s0, s4); s8 = add2(s8, sd);
            ull pre2 = add2(s0, s8);
#pragma unroll
            for (int i = 0; i < NI; ++i) {
                float wv = ldsf(sb + OFF_WINP + (uint32_t)(n * NI + i) * 4);
                ull x2 = ldsu64(sb + OFF_XSHT + (uint32_t)(i * 8 + 2 * rp) * 4);
                pre2 = fma2(dup2(wv), x2, pre2);
            }

            float plo, phi, slo, shi;
            unpack2(pre2, plo, phi);
            unpack2(ldsu64(aScur + (uint32_t)(gn * 8 + 2 * rp) * 4), slo, shi);
            float nlo = 0.9f * slo + 0.1f * (fmaxf(plo, 0.0f) + rn0);
            float nhi = 0.9f * shi + 0.1f * (fmaxf(phi, 0.0f) + rn1);

            size_t so = (size_t)(t + 1) * NN + gn;
            states[(size_t)b0 * TT * NN + so] = nlo;
            states[(size_t)b1 * TT * NN + so] = nhi;

            // broadcast s_new slice into every rank's next buffer
            ull snew2 = pack2(nlo, nhi);
            uint32_t dsto = aSnxt + (uint32_t)(gn * 8 + 2 * rp) * 4;
#pragma unroll
            for (int cr = 0; cr < 8; ++cr) {
                uint32_t ra;
                asm volatile("mapa.shared::cluster.u32 %0,%1,%2;" : "=r"(ra) : "r"(dsto), "r"(cr));
                asm volatile("st.shared::cluster.u64 [%0],%1;" :: "r"(ra), "l"(snew2) : "memory");
            }
        }

        // ---- cluster barrier: release DSMEM stores, sync all 8 CTAs ----
        asm volatile("barrier.cluster.arrive.aligned;" ::: "memory");
        asm volatile("barrier.cluster.wait.aligned;" ::: "memory");
    }
}

// ============================================================================
// Kernel B: outputs[b,t] = dot(states[b,t,:], W_out). One warp per (b,t).
// ============================================================================
__global__ void __launch_bounds__(256) out_proj_kernel(
    const float* __restrict__ states,
    const float* __restrict__ W_out,
    float* __restrict__ out)
{
    int warp = (blockIdx.x * blockDim.x + threadIdx.x) >> 5;  // 0 .. B*T-1
    int lane = threadIdx.x & 31;
    const float4* sp = (const float4*)(states + (size_t)warp * NN);
    const float4* wp = (const float4*)W_out;
    float acc = 0.0f;
#pragma unroll
    for (int i = 0; i < 4; ++i) {
        float4 s = sp[lane + 32 * i];
        float4 v = wp[lane + 32 * i];
        acc += s.x * v.x + s.y * v.y + s.z * v.z + s.w * v.w;
    }
#pragma unroll
    for (int o = 16; o; o >>= 1) acc += __shfl_xor_sync(0xFFFFFFFFu, acc, o);
    if (lane == 0) out[warp] = acc;
}

// ============================================================================
extern "C" void kernel_launch(void* const* d_in, const int* in_sizes, int n_in,
                              void* d_out, int out_size)
{
    const float* u         = (const float*)d_in[0];
    const float* rec_noise = (const float*)d_in[1];
    const float* inp_noise = (const float*)d_in[2];
    const float* W_rec     = (const float*)d_in[3];
    const float* W_inp     = (const float*)d_in[4];
    const float* W_out     = (const float*)d_in[5];
    const float* y_init    = (const float*)d_in[6];

    float* states  = (float*)d_out;                          // (B,T,N)
    float* outputs = states + (size_t)BB * TT * NN;          // (B,T,1)

    cudaFuncSetAttribute(rnn_dyn_kernel,
                         cudaFuncAttributeMaxDynamicSharedMemorySize, SMEM_TOTAL);

    rnn_dyn_kernel<<<CTAS, THREADS, SMEM_TOTAL>>>(
        u, rec_noise, inp_noise, W_rec, W_inp, y_init, states);

    out_proj_kernel<<<(BB * TT) / 8, 256>>>(states, W_out, outputs);
}